// round 8
// baseline (speedup 1.0000x reference)
#include <cuda_runtime.h>
#include <math.h>

#define GAMMA 3.4f
#define EPS 1e-8f
#define B_DIM 2048
#define P_TOK 197
#define P_USE 196
#define D_DIM 768
#define NWARP 7
#define NTHREADS (NWARP * 32)      // 224
#define NSPLIT 4                   // blocks per batch
#define PPB (P_USE / NSPLIT)       // 49 patches per block
#define PPW (PPB / NWARP)          // 7 patches per warp
#define NBLOCKS (B_DIM * NSPLIT)   // 8192

__device__ double g_acc;           // zero-initialized
__device__ unsigned int g_count;

__global__ __launch_bounds__(NTHREADS, 4) void loss_fused_kernel(
    const float* __restrict__ patch_tokens,
    const float* __restrict__ out_text,
    const float* __restrict__ gt,
    float* __restrict__ out)
{
    __shared__ float4 s_ot[D_DIM / 4];    // 3 KB
    __shared__ float  s_gt[PPB];
    __shared__ float  s_otn;
    __shared__ float  warp_sum[NWARP];

    const int b     = blockIdx.x;
    const int quart = blockIdx.y;          // 0..3
    const int tid   = threadIdx.x;
    const int warp  = tid >> 5;
    const int lane  = tid & 31;
    const int pbase = quart * PPB;
    const int p0    = pbase + warp * PPW;

    // ── Prefetch first patch row IMMEDIATELY (independent of smem staging)
    // so DRAM stays busy through the whole prologue.
    const float4* row0 = reinterpret_cast<const float4*>(
        patch_tokens + ((size_t)b * P_TOK + (size_t)(p0 + 1)) * D_DIM);
    float4 v[6];
#pragma unroll
    for (int j = 0; j < 6; ++j) v[j] = __ldcs(&row0[lane + 32 * j]);

    // Stage out_text[b] and this quarter's gt slice into smem (coalesced).
    const float4* ot4 = reinterpret_cast<const float4*>(out_text + (size_t)b * D_DIM);
    if (tid < D_DIM / 4) s_ot[tid] = __ldg(&ot4[tid]);
    if (tid < PPB) s_gt[tid] = __ldg(&gt[(size_t)b * P_USE + pbase + tid]);
    __syncthreads();

    if (warp == 0) {
        float otn2 = 0.f;
#pragma unroll
        for (int j = 0; j < 6; ++j) {
            float4 q = s_ot[lane + 32 * j];
            otn2 += q.x * q.x + q.y * q.y + q.z * q.z + q.w * q.w;
        }
#pragma unroll
        for (int off = 16; off > 0; off >>= 1)
            otn2 += __shfl_xor_sync(0xffffffffu, otn2, off);
        if (lane == 0) s_otn = fmaxf(sqrtf(otn2), EPS);
    }
    __syncthreads();
    const float ot_n = s_otn;

    float local = 0.f;

    for (int i = 0; i < PPW; ++i) {
        const int p = p0 + i;

        // Prefetch next row while reducing the current one.
        float4 w[6];
        if (i + 1 < PPW) {
            const float4* rown = reinterpret_cast<const float4*>(
                patch_tokens + ((size_t)b * P_TOK + (size_t)(p + 2)) * D_DIM);
#pragma unroll
            for (int j = 0; j < 6; ++j) w[j] = __ldcs(&rown[lane + 32 * j]);
        }

        float dot = 0.f, nn = 0.f;
#pragma unroll
        for (int j = 0; j < 6; ++j) {
            float4 q = s_ot[lane + 32 * j];
            dot += v[j].x * q.x + v[j].y * q.y + v[j].z * q.z + v[j].w * q.w;
            nn  += v[j].x * v[j].x + v[j].y * v[j].y + v[j].z * v[j].z + v[j].w * v[j].w;
        }
#pragma unroll
        for (int off = 16; off > 0; off >>= 1) {
            dot += __shfl_xor_sync(0xffffffffu, dot, off);
            nn  += __shfl_xor_sync(0xffffffffu, nn,  off);
        }

        if (lane == 0) {
            const float pt_n = fmaxf(sqrtf(nn), EPS);
            const float cosv = dot / (pt_n * ot_n);
            const float vec  = 1.0f / (1.0f + expf(cosv - 1.0f));   // sigmoid(1-cos)
            const float gtv  = s_gt[p - pbase] * (1.0f / 255.0f);
            const float diff = fabsf(vec - gtv);
            local += -logf(1.0f - diff) * (gtv * GAMMA + 1.0f);
        }

#pragma unroll
        for (int j = 0; j < 6; ++j) v[j] = w[j];
    }

    if (lane == 0) warp_sum[warp] = local;
    __syncthreads();

    if (tid == 0) {
        float s = 0.f;
#pragma unroll
        for (int w2 = 0; w2 < NWARP; ++w2) s += warp_sum[w2];
        atomicAdd(&g_acc, (double)s);

        __threadfence();
        unsigned int arrived = atomicAdd(&g_count, 1u);
        if (arrived == NBLOCKS - 1) {
            double total = atomicAdd(&g_acc, 0.0);
            out[0] = (float)(total / (double)B_DIM);
            g_acc = 0.0;
            g_count = 0u;
        }
    }
}

extern "C" void kernel_launch(void* const* d_in, const int* in_sizes, int n_in,
                              void* d_out, int out_size) {
    const float* patch_tokens = (const float*)d_in[0];
    const float* out_text     = (const float*)d_in[1];
    const float* gt           = (const float*)d_in[2];
    float* out = (float*)d_out;

    dim3 grid(B_DIM, NSPLIT);   // 2048 x 4
    loss_fused_kernel<<<grid, NTHREADS>>>(patch_tokens, out_text, gt, out);
}

// round 9
// speedup vs baseline: 1.0046x; 1.0046x over previous
#include <cuda_runtime.h>
#include <math.h>

#define GAMMA 3.4f
#define EPS 1e-8f
#define B_DIM 2048
#define P_TOK 197
#define P_USE 196
#define D_DIM 768
#define NWARP 7
#define NTHREADS (NWARP * 32)      // 224
#define NSPLIT 7                   // blocks per batch
#define PPB (P_USE / NSPLIT)       // 28 patches per block
#define PPW (PPB / NWARP)          // 4 patches per warp
#define NBLOCKS (B_DIM * NSPLIT)   // 14336

__device__ double g_acc;           // zero-initialized
__device__ unsigned int g_count;

__global__ __launch_bounds__(NTHREADS, 4) void loss_fused_kernel(
    const float* __restrict__ patch_tokens,
    const float* __restrict__ out_text,
    const float* __restrict__ gt,
    float* __restrict__ out)
{
    __shared__ float4 s_ot[D_DIM / 4];    // 3 KB
    __shared__ float  s_gt[PPB];
    __shared__ float  s_otn;
    __shared__ float  warp_sum[NWARP];

    const int b     = blockIdx.x;
    const int chunk = blockIdx.y;          // 0..6
    const int tid   = threadIdx.x;
    const int warp  = tid >> 5;
    const int lane  = tid & 31;
    const int pbase = chunk * PPB;
    const int p0    = pbase + warp * PPW;

    // ── Prefetch first patch row IMMEDIATELY (independent of smem staging)
    // so DRAM stays busy through the whole prologue.
    const float4* row0 = reinterpret_cast<const float4*>(
        patch_tokens + ((size_t)b * P_TOK + (size_t)(p0 + 1)) * D_DIM);
    float4 v[6];
#pragma unroll
    for (int j = 0; j < 6; ++j) v[j] = __ldcs(&row0[lane + 32 * j]);

    // Stage out_text[b] and this chunk's gt slice into smem (coalesced).
    const float4* ot4 = reinterpret_cast<const float4*>(out_text + (size_t)b * D_DIM);
    if (tid < D_DIM / 4) s_ot[tid] = __ldg(&ot4[tid]);
    if (tid < PPB) s_gt[tid] = __ldg(&gt[(size_t)b * P_USE + pbase + tid]);
    __syncthreads();

    if (warp == 0) {
        float otn2 = 0.f;
#pragma unroll
        for (int j = 0; j < 6; ++j) {
            float4 q = s_ot[lane + 32 * j];
            otn2 += q.x * q.x + q.y * q.y + q.z * q.z + q.w * q.w;
        }
#pragma unroll
        for (int off = 16; off > 0; off >>= 1)
            otn2 += __shfl_xor_sync(0xffffffffu, otn2, off);
        if (lane == 0) s_otn = fmaxf(sqrtf(otn2), EPS);
    }
    __syncthreads();
    const float ot_n = s_otn;

    float local = 0.f;

#pragma unroll
    for (int i = 0; i < PPW; ++i) {
        const int p = p0 + i;

        // Prefetch next row while reducing the current one.
        float4 w[6];
        if (i + 1 < PPW) {
            const float4* rown = reinterpret_cast<const float4*>(
                patch_tokens + ((size_t)b * P_TOK + (size_t)(p + 2)) * D_DIM);
#pragma unroll
            for (int j = 0; j < 6; ++j) w[j] = __ldcs(&rown[lane + 32 * j]);
        }

        float dot = 0.f, nn = 0.f;
#pragma unroll
        for (int j = 0; j < 6; ++j) {
            float4 q = s_ot[lane + 32 * j];
            dot += v[j].x * q.x + v[j].y * q.y + v[j].z * q.z + v[j].w * q.w;
            nn  += v[j].x * v[j].x + v[j].y * v[j].y + v[j].z * v[j].z + v[j].w * v[j].w;
        }
#pragma unroll
        for (int off = 16; off > 0; off >>= 1) {
            dot += __shfl_xor_sync(0xffffffffu, dot, off);
            nn  += __shfl_xor_sync(0xffffffffu, nn,  off);
        }

        if (lane == 0) {
            const float pt_n = fmaxf(sqrtf(nn), EPS);
            const float cosv = dot / (pt_n * ot_n);
            const float vec  = 1.0f / (1.0f + __expf(cosv - 1.0f));   // sigmoid(1-cos)
            const float gtv  = s_gt[p - pbase] * (1.0f / 255.0f);
            const float diff = fabsf(vec - gtv);
            local += -__logf(1.0f - diff) * (gtv * GAMMA + 1.0f);
        }

#pragma unroll
        for (int j = 0; j < 6; ++j) v[j] = w[j];
    }

    if (lane == 0) warp_sum[warp] = local;
    __syncthreads();

    if (tid == 0) {
        float s = 0.f;
#pragma unroll
        for (int w2 = 0; w2 < NWARP; ++w2) s += warp_sum[w2];
        atomicAdd(&g_acc, (double)s);

        __threadfence();
        unsigned int arrived = atomicAdd(&g_count, 1u);
        if (arrived == NBLOCKS - 1) {
            double total = atomicAdd(&g_acc, 0.0);
            out[0] = (float)(total / (double)B_DIM);
            g_acc = 0.0;
            g_count = 0u;
        }
    }
}

extern "C" void kernel_launch(void* const* d_in, const int* in_sizes, int n_in,
                              void* d_out, int out_size) {
    const float* patch_tokens = (const float*)d_in[0];
    const float* out_text     = (const float*)d_in[1];
    const float* gt           = (const float*)d_in[2];
    float* out = (float*)d_out;

    dim3 grid(B_DIM, NSPLIT);   // 2048 x 7
    loss_fused_kernel<<<grid, NTHREADS>>>(patch_tokens, out_text, gt, out);
}

// round 11
// speedup vs baseline: 1.0116x; 1.0070x over previous
#include <cuda_runtime.h>
#include <math.h>

#define GAMMA 3.4f
#define EPS 1e-8f
#define B_DIM 2048
#define P_TOK 197
#define P_USE 196
#define D_DIM 768
#define NWARP 7
#define NTHREADS (NWARP * 32)      // 224
#define NSPLIT 7                   // blocks per batch
#define PPB (P_USE / NSPLIT)       // 28 patches per block
#define PPW 4                      // 4 patches per warp, 8 lanes each
#define NBLOCKS (B_DIM * NSPLIT)   // 14336

__device__ double g_acc;           // zero-initialized
__device__ unsigned int g_count;

__global__ __launch_bounds__(NTHREADS, 4) void loss_fused_kernel(
    const float* __restrict__ patch_tokens,
    const float* __restrict__ out_text,
    const float* __restrict__ gt,
    float* __restrict__ out)
{
    __shared__ float warp_part[NWARP];

    const int b     = blockIdx.x;
    const int chunk = blockIdx.y;          // 0..6
    const int tid   = threadIdx.x;
    const int warp  = tid >> 5;
    const int lane  = tid & 31;
    const int sub   = lane >> 3;           // 8-lane group id: 0..3
    const int gl    = lane & 7;            // lane within group

    // This lane's patch: 4 patches per warp, one per 8-lane group.
    const int p = chunk * PPB + warp * PPW + sub;

    const float4* row = reinterpret_cast<const float4*>(
        patch_tokens + ((size_t)b * P_TOK + (size_t)(p + 1)) * D_DIM);
    const float4* ot4 = reinterpret_cast<const float4*>(out_text + (size_t)b * D_DIM);

    // Stream the whole row: 24 float4 per lane (group covers 192 float4).
    // No barriers anywhere before this — loads start at cycle 0.
    float dot = 0.f, nn = 0.f, qn = 0.f;
#pragma unroll
    for (int j = 0; j < 24; ++j) {
        float4 v = __ldcs(&row[gl + 8 * j]);
        float4 q = __ldg(&ot4[gl + 8 * j]);    // L1/L2-resident, shared by 4 groups
        dot += v.x * q.x + v.y * q.y + v.z * q.z + v.w * q.w;
        nn  += v.x * v.x + v.y * v.y + v.z * v.z + v.w * v.w;
        qn  += q.x * q.x + q.y * q.y + q.z * q.z + q.w * q.w;
    }

    // Reduce within each 8-lane group: 3 butterfly steps, all 4 patches at once.
#pragma unroll
    for (int off = 4; off > 0; off >>= 1) {
        dot += __shfl_xor_sync(0xffffffffu, dot, off);
        nn  += __shfl_xor_sync(0xffffffffu, nn,  off);
        qn  += __shfl_xor_sync(0xffffffffu, qn,  off);
    }

    // Scalar loss on 4 lanes (gl==0) in parallel.
    float term = 0.f;
    if (gl == 0) {
        const float ot_n = fmaxf(sqrtf(qn), EPS);
        const float pt_n = fmaxf(sqrtf(nn), EPS);
        const float cosv = dot / (pt_n * ot_n);
        const float vec  = 1.0f / (1.0f + __expf(cosv - 1.0f));   // sigmoid(1-cos)
        const float gtv  = __ldg(&gt[(size_t)b * P_USE + p]) * (1.0f / 255.0f);
        const float diff = fabsf(vec - gtv);
        term = -__logf(1.0f - diff) * (gtv * GAMMA + 1.0f);
    }
    // Sum the 4 group results to lane 0.
    term += __shfl_xor_sync(0xffffffffu, term, 8);
    term += __shfl_xor_sync(0xffffffffu, term, 16);

    if (lane == 0) warp_part[warp] = term;
    __syncthreads();

    if (tid == 0) {
        float s = 0.f;
#pragma unroll
        for (int w = 0; w < NWARP; ++w) s += warp_part[w];
        atomicAdd(&g_acc, (double)s);

        __threadfence();
        unsigned int arrived = atomicAdd(&g_count, 1u);
        if (arrived == NBLOCKS - 1) {
            double total = atomicAdd(&g_acc, 0.0);
            out[0] = (float)(total / (double)B_DIM);
            g_acc = 0.0;
            g_count = 0u;
        }
    }
}

extern "C" void kernel_launch(void* const* d_in, const int* in_sizes, int n_in,
                              void* d_out, int out_size) {
    const float* patch_tokens = (const float*)d_in[0];
    const float* out_text     = (const float*)d_in[1];
    const float* gt           = (const float*)d_in[2];
    float* out = (float*)d_out;

    dim3 grid(B_DIM, NSPLIT);   // 2048 x 7
    loss_fused_kernel<<<grid, NTHREADS>>>(patch_tokens, out_text, gt, out);
}